// round 17
// speedup vs baseline: 4.0871x; 1.0154x over previous
#include <cuda_runtime.h>
#include <cuda_bf16.h>
#include <cuda_fp16.h>
#include <cstdint>
typedef __nv_bfloat16 bf16;
typedef __half f16;

#define B_   2
#define T_   4096
#define D_   1024
#define H_   16
#define DH_  64
#define FD_  512
#define BH_  (B_*H_)
#define SZ_BTD ((size_t)B_*T_*D_)
#define SZ_F   ((size_t)BH_*T_*FD_)

// fp32 scratch
#define OFF_Q   ((size_t)0)
#define OFF_K   (SZ_BTD)
#define OFF_SCQ (2*SZ_BTD)
#define OFF_SCK (OFF_SCQ + (size_t)BH_*T_)
#define OFF_AL  (OFF_SCK + (size_t)BH_*T_)
#define OFF_BE  (OFF_AL + BH_)
#define OFF_SR  (OFF_BE + BH_)
__device__ float g_buf[OFF_SR + (size_t)B_*T_];

// 2-byte scratch
#define BO_XH    ((size_t)0)
#define BO_XL    (SZ_BTD)
#define BO_WQH   (2*SZ_BTD)
#define BO_WQL   (BO_WQH + (size_t)D_*D_)
#define BO_WK    (BO_WQL + (size_t)D_*D_)
#define BO_WV    (BO_WK + (size_t)D_*D_)
#define BO_WO    (BO_WV + (size_t)D_*D_)
#define BO_RF    (BO_WO + (size_t)D_*D_)
#define BO_QF    (BO_RF + 16384)
#define BO_KFT   (BO_QF + SZ_F)
#define BO_VT    (BO_KFT + SZ_F)                  // [bh][80][T]; row64=ones
#define BO_KVT   (BO_VT + (size_t)BH_*80*T_)
#define BO_AH    (BO_KVT + (size_t)BH_*80*FD_)
__device__ bf16 g_bf[BO_AH + SZ_BTD];

__device__ __forceinline__ uint32_t smem_to_u32(const void* p) {
    uint32_t a;
    asm("{ .reg .u64 t; cvta.to.shared.u64 t, %1; cvt.u32.u64 %0, t; }" : "=r"(a) : "l"(p));
    return a;
}
#define SWZ(o) ((o) ^ (((o) >> 3) & 0x70))
__device__ __forceinline__ void cp_async16(uint32_t s, const void* g) {
    asm volatile("cp.async.cg.shared.global [%0], [%1], 16;" :: "r"(s), "l"(g));
}
__device__ __forceinline__ void cp_commit() { asm volatile("cp.async.commit_group;" ::: "memory"); }
template <int N> __device__ __forceinline__ void cp_wait() {
    asm volatile("cp.async.wait_group %0;" :: "n"(N) : "memory");
}
__device__ __forceinline__ void ldsm_x4(uint32_t& r0, uint32_t& r1, uint32_t& r2, uint32_t& r3, uint32_t a) {
    asm volatile("ldmatrix.sync.aligned.m8n8.x4.shared.b16 {%0,%1,%2,%3}, [%4];"
                 : "=r"(r0), "=r"(r1), "=r"(r2), "=r"(r3) : "r"(a));
}
__device__ __forceinline__ void ldsm_x2(uint32_t& r0, uint32_t& r1, uint32_t a) {
    asm volatile("ldmatrix.sync.aligned.m8n8.x2.shared.b16 {%0,%1}, [%2];"
                 : "=r"(r0), "=r"(r1) : "r"(a));
}
__device__ __forceinline__ void mma_f16(float* c, const uint32_t* a, const uint32_t* b) {
    asm volatile("mma.sync.aligned.m16n8k16.row.col.f32.f16.f16.f32 "
                 "{%0,%1,%2,%3}, {%4,%5,%6,%7}, {%8,%9}, {%0,%1,%2,%3};"
                 : "+f"(c[0]), "+f"(c[1]), "+f"(c[2]), "+f"(c[3])
                 : "r"(a[0]), "r"(a[1]), "r"(a[2]), "r"(a[3]), "r"(b[0]), "r"(b[1]));
}
__device__ __forceinline__ void store_pair_h(f16* ph, f16* pl, size_t off, float x0, float x1) {
    f16 h0 = __float2half_rn(x0), h1 = __float2half_rn(x1);
    __half2 hp = __halves2half2(h0, h1);
    *(uint32_t*)(ph + off) = *(uint32_t*)&hp;
    __half2 lp = __halves2half2(__float2half_rn(x0 - __half2float(h0)),
                                __float2half_rn(x1 - __half2float(h1)));
    *(uint32_t*)(pl + off) = *(uint32_t*)&lp;
}
__device__ __forceinline__ void store_h2(f16* p, size_t off, float x0, float x1) {
    __half2 hp = __halves2half2(__float2half_rn(x0), __float2half_rn(x1));
    *(uint32_t*)(p + off) = *(uint32_t*)&hp;
}
__device__ __forceinline__ void fast_sincos(float x, float& s, float& c) {
    float kf = rintf(x * 0.63661977f);
    int q = (int)kf;
    float r = fmaf(kf, -1.5707963705062866f, x);
    r = fmaf(kf, 4.3711388286738e-8f, r);
    float r2 = r * r;
    float sp = fmaf(-1.98412698e-4f, r2, 8.33333333e-3f);
    sp = fmaf(sp, r2, -1.66666667e-1f) * r2;
    float sr = fmaf(sp, r, r);
    float cp = fmaf(2.48015873e-5f, r2, -1.38888889e-3f);
    cp = fmaf(cp, r2, 4.16666667e-2f);
    cp = fmaf(cp, r2, -0.5f);
    float cr = fmaf(cp, r2, 1.0f);
    if (q & 1) { float t = sr; sr = cr; cr = -t; }
    if (q & 2) { sr = -sr; cr = -cr; }
    s = sr; c = cr;
}

#define TILE_B 16384
#define BUF3   (4*TILE_B)
#define BUF2   (3*TILE_B)
#define BUF1   (2*TILE_B)
#define SMEM_PROJ (2*BUF3)

// ======== uber projection kernel: z=0 Q(3-pass), z=1 K(2-pass), z=2 V(1-pass + VT) ========
__global__ void __launch_bounds__(256)
proj_all(const f16* __restrict__ xh, const f16* __restrict__ xl,
         const f16* __restrict__ wqh, const f16* __restrict__ wql,
         const f16* __restrict__ wk16, const f16* __restrict__ wv16,
         float* __restrict__ Qp, float* __restrict__ Kp, f16* __restrict__ VT)
{
    extern __shared__ char smem[];
    const uint32_t sb = smem_to_u32(smem);
    const int tid = threadIdx.x, wid = tid >> 5, lane = tid & 31;
    const int bn = blockIdx.x << 7, bm = blockIdx.y << 7;
    const int wm = (wid >> 2) << 6, wn = (wid & 3) << 5;
    const int K = D_, N = D_;
    const int nchunk = K >> 6;
    const int lr = lane & 15, lc = lane >> 4, br = lane & 7, bk = (lane >> 3) & 1;
    float acc[4][4][4];
#pragma unroll
    for (int i = 0; i < 4; i++)
#pragma unroll
        for (int j = 0; j < 4; j++)
#pragma unroll
            for (int r = 0; r < 4; r++) acc[i][j][r] = 0.f;

    if (blockIdx.z == 0) {
        const f16* gs[4] = {xh, xl, wqh, wql};
        const int rb[4] = {bm, bm, bn, bn};
        auto load = [&](int kc, int buf) {
            uint32_t base = sb + buf * BUF3;
            int ke = kc << 6;
#pragma unroll
            for (int t = 0; t < 4; t++)
#pragma unroll
                for (int i = 0; i < 4; i++) {
                    int idx = tid + (i << 8), r = idx >> 3, c = idx & 7;
                    cp_async16(base + t * TILE_B + SWZ(r * 128 + c * 16),
                               gs[t] + (size_t)(rb[t] + r) * K + ke + c * 8);
                }
        };
        load(0, 0); cp_commit();
        for (int kc = 0; kc < nchunk; kc++) {
            int cur = kc & 1;
            if (kc + 1 < nchunk) { load(kc + 1, cur ^ 1); cp_commit(); cp_wait<1>(); }
            else cp_wait<0>();
            __syncthreads();
            uint32_t bA = sb + cur * BUF3;
#pragma unroll
            for (int ks = 0; ks < 4; ks++) {
                uint32_t a_h[4][4], a_l[4][4], b_h[4][2], b_l[4][2];
#pragma unroll
                for (int i = 0; i < 4; i++) {
                    uint32_t o = SWZ((wm + i * 16 + lr) * 128 + ks * 32 + lc * 16);
                    ldsm_x4(a_h[i][0], a_h[i][1], a_h[i][2], a_h[i][3], bA + o);
                    ldsm_x4(a_l[i][0], a_l[i][1], a_l[i][2], a_l[i][3], bA + TILE_B + o);
                }
#pragma unroll
                for (int j = 0; j < 4; j++) {
                    uint32_t o = SWZ((wn + j * 8 + br) * 128 + ks * 32 + bk * 16);
                    ldsm_x2(b_h[j][0], b_h[j][1], bA + 2 * TILE_B + o);
                    ldsm_x2(b_l[j][0], b_l[j][1], bA + 3 * TILE_B + o);
                }
#pragma unroll
                for (int i = 0; i < 4; i++)
#pragma unroll
                    for (int j = 0; j < 4; j++) {
                        mma_f16(acc[i][j], a_h[i], b_h[j]);
                        mma_f16(acc[i][j], a_h[i], b_l[j]);
                        mma_f16(acc[i][j], a_l[i], b_h[j]);
                    }
            }
            __syncthreads();
        }
#pragma unroll
        for (int i = 0; i < 4; i++) {
            int row = bm + wm + i * 16 + (lane >> 2);
#pragma unroll
            for (int j = 0; j < 4; j++) {
                int col = bn + wn + j * 8 + ((lane & 3) << 1);
                *(float2*)&Qp[(size_t)row * N + col]       = make_float2(acc[i][j][0], acc[i][j][1]);
                *(float2*)&Qp[(size_t)(row + 8) * N + col] = make_float2(acc[i][j][2], acc[i][j][3]);
            }
        }
    } else if (blockIdx.z == 1) {
        auto load = [&](int kc, int buf) {
            uint32_t base = sb + buf * BUF2;
            int ke = kc << 6;
#pragma unroll
            for (int i = 0; i < 4; i++) {
                int idx = tid + (i << 8), r = idx >> 3, c = idx & 7;
                uint32_t so = SWZ(r * 128 + c * 16);
                cp_async16(base + so,              xh + (size_t)(bm + r) * K + ke + c * 8);
                cp_async16(base + TILE_B + so,     xl + (size_t)(bm + r) * K + ke + c * 8);
                cp_async16(base + 2 * TILE_B + so, wk16 + (size_t)(bn + r) * K + ke + c * 8);
            }
        };
        load(0, 0); cp_commit();
        for (int kc = 0; kc < nchunk; kc++) {
            int cur = kc & 1;
            if (kc + 1 < nchunk) { load(kc + 1, cur ^ 1); cp_commit(); cp_wait<1>(); }
            else cp_wait<0>();
            __syncthreads();
            uint32_t bA = sb + cur * BUF2;
#pragma unroll
            for (int ks = 0; ks < 4; ks++) {
                uint32_t a_h[4][4], a_l[4][4], b_[4][2];
#pragma unroll
                for (int i = 0; i < 4; i++) {
                    uint32_t o = SWZ((wm + i * 16 + lr) * 128 + ks * 32 + lc * 16);
                    ldsm_x4(a_h[i][0], a_h[i][1], a_h[i][2], a_h[i][3], bA + o);
                    ldsm_x4(a_l[i][0], a_l[i][1], a_l[i][2], a_l[i][3], bA + TILE_B + o);
                }
#pragma unroll
                for (int j = 0; j < 4; j++) {
                    uint32_t o = SWZ((wn + j * 8 + br) * 128 + ks * 32 + bk * 16);
                    ldsm_x2(b_[j][0], b_[j][1], bA + 2 * TILE_B + o);
                }
#pragma unroll
                for (int i = 0; i < 4; i++)
#pragma unroll
                    for (int j = 0; j < 4; j++) {
                        mma_f16(acc[i][j], a_h[i], b_[j]);
                        mma_f16(acc[i][j], a_l[i], b_[j]);
                    }
            }
            __syncthreads();
        }
#pragma unroll
        for (int i = 0; i < 4; i++) {
            int row = bm + wm + i * 16 + (lane >> 2);
#pragma unroll
            for (int j = 0; j < 4; j++) {
                int col = bn + wn + j * 8 + ((lane & 3) << 1);
                *(float2*)&Kp[(size_t)row * N + col]       = make_float2(acc[i][j][0], acc[i][j][1]);
                *(float2*)&Kp[(size_t)(row + 8) * N + col] = make_float2(acc[i][j][2], acc[i][j][3]);
            }
        }
    } else {
        auto load = [&](int kc, int buf) {
            uint32_t base = sb + buf * BUF1;
            int ke = kc << 6;
#pragma unroll
            for (int i = 0; i < 4; i++) {
                int idx = tid + (i << 8), r = idx >> 3, c = idx & 7;
                uint32_t so = SWZ(r * 128 + c * 16);
                cp_async16(base + so,          xh + (size_t)(bm + r) * K + ke + c * 8);
                cp_async16(base + TILE_B + so, wv16 + (size_t)(bn + r) * K + ke + c * 8);
            }
        };
        load(0, 0); cp_commit();
        for (int kc = 0; kc < nchunk; kc++) {
            int cur = kc & 1;
            if (kc + 1 < nchunk) { load(kc + 1, cur ^ 1); cp_commit(); cp_wait<1>(); }
            else cp_wait<0>();
            __syncthreads();
            uint32_t bA = sb + cur * BUF1;
#pragma unroll
            for (int ks = 0; ks < 4; ks++) {
                uint32_t a_[4][4], b_[4][2];
#pragma unroll
                for (int i = 0; i < 4; i++) {
                    uint32_t o = SWZ((wm + i * 16 + lr) * 128 + ks * 32 + lc * 16);
                    ldsm_x4(a_[i][0], a_[i][1], a_[i][2], a_[i][3], bA + o);
                }
#pragma unroll
                for (int j = 0; j < 4; j++) {
                    uint32_t o = SWZ((wn + j * 8 + br) * 128 + ks * 32 + bk * 16);
                    ldsm_x2(b_[j][0], b_[j][1], bA + TILE_B + o);
                }
#pragma unroll
                for (int i = 0; i < 4; i++)
#pragma unroll
                    for (int j = 0; j < 4; j++)
                        mma_f16(acc[i][j], a_[i], b_[j]);
            }
            __syncthreads();
        }
        float* stage = (float*)smem;
#pragma unroll
        for (int i = 0; i < 4; i++) {
            int row = wm + i * 16 + (lane >> 2);
#pragma unroll
            for (int j = 0; j < 4; j++) {
                int col = wn + j * 8 + ((lane & 3) << 1);
                stage[col * 132 + row]           = acc[i][j][0];
                stage[(col + 1) * 132 + row]     = acc[i][j][1];
                stage[col * 132 + row + 8]       = acc[i][j][2];
                stage[(col + 1) * 132 + row + 8] = acc[i][j][3];
            }
        }
        __syncthreads();
        int b = bm >> 12;
        int dl = tid >> 1, ts = (tid & 1) << 6;
        int h = (bn + dl) >> 6, v = (bn + dl) & 63;
        size_t base = ((size_t)(b * H_ + h) * 80 + v) * T_ + (bm & 4095) + ts;
#pragma unroll
        for (int p = 0; p < 32; p++)
            store_h2(VT, base + p * 2, stage[dl * 132 + ts + p * 2], stage[dl * 132 + ts + p * 2 + 1]);
    }
}

// ======== fp16 1-pass GEMM with row scale (O projection) ========
#define SMEM_G1 (2*BUF1)
__global__ void __launch_bounds__(256)
gemm1(const f16* __restrict__ Am, const f16* __restrict__ Bm,
      const float* __restrict__ S, float* __restrict__ C, int M, int N, int K)
{
    extern __shared__ char smem[];
    const uint32_t sb = smem_to_u32(smem);
    const int tid = threadIdx.x, wid = tid >> 5, lane = tid & 31;
    const int bn = blockIdx.x << 7, bm = blockIdx.y << 7;
    const int wm = (wid >> 2) << 6, wn = (wid & 3) << 5;
    const int nchunk = K >> 6;
    const int lr = lane & 15, lc = lane >> 4, br = lane & 7, bk = (lane >> 3) & 1;
    float acc[4][4][4];
#pragma unroll
    for (int i = 0; i < 4; i++)
#pragma unroll
        for (int j = 0; j < 4; j++)
#pragma unroll
            for (int r = 0; r < 4; r++) acc[i][j][r] = 0.f;
    auto load = [&](int kc, int buf) {
        uint32_t base = sb + buf * BUF1;
        int ke = kc << 6;
#pragma unroll
        for (int i = 0; i < 4; i++) {
            int idx = tid + (i << 8), r = idx >> 3, c = idx & 7;
            uint32_t so = SWZ(r * 128 + c * 16);
            cp_async16(base + so,          Am + (size_t)(bm + r) * K + ke + c * 8);
            cp_async16(base + TILE_B + so, Bm + (size_t)(bn + r) * K + ke + c * 8);
        }
    };
    load(0, 0); cp_commit();
    for (int kc = 0; kc < nchunk; kc++) {
        int cur = kc & 1;
        if (kc + 1 < nchunk) { load(kc + 1, cur ^ 1); cp_commit(); cp_wait<1>(); }
        else cp_wait<0>();
        __syncthreads();
        uint32_t bA = sb + cur * BUF1;
#pragma unroll
        for (int ks = 0; ks < 4; ks++) {
            uint32_t a_[4][4], b_[4][2];
#pragma unroll
            for (int i = 0; i < 4; i++) {
                uint32_t o = SWZ((wm + i * 16 + lr) * 128 + ks * 32 + lc * 16);
                ldsm_x4(a_[i][0], a_[i][1], a_[i][2], a_[i][3], bA + o);
            }
#pragma unroll
            for (int j = 0; j < 4; j++) {
                uint32_t o = SWZ((wn + j * 8 + br) * 128 + ks * 32 + bk * 16);
                ldsm_x2(b_[j][0], b_[j][1], bA + TILE_B + o);
            }
#pragma unroll
            for (int i = 0; i < 4; i++)
#pragma unroll
                for (int j = 0; j < 4; j++)
                    mma_f16(acc[i][j], a_[i], b_[j]);
        }
        __syncthreads();
    }
#pragma unroll
    for (int i = 0; i < 4; i++) {
        int row = bm + wm + i * 16 + (lane >> 2);
        float s0 = S[row], s1 = S[row + 8];
#pragma unroll
        for (int j = 0; j < 4; j++) {
            int col = bn + wn + j * 8 + ((lane & 3) << 1);
            *(float2*)&C[(size_t)row * N + col]       = make_float2(acc[i][j][0] * s0, acc[i][j][1] * s0);
            *(float2*)&C[(size_t)(row + 8) * N + col] = make_float2(acc[i][j][2] * s1, acc[i][j][3] * s1);
        }
    }
}

// ======== merged conversions: x split (8192 blk), wq split (1024), wk/wv/wo conv (1024 ea), rf (16) ========
__global__ void __launch_bounds__(256)
conv_all(const float* __restrict__ x, const float* __restrict__ wq,
         const float* __restrict__ wk, const float* __restrict__ wv,
         const float* __restrict__ wo, const float* __restrict__ rf,
         f16* __restrict__ xh, f16* __restrict__ xl,
         f16* __restrict__ wqh, f16* __restrict__ wql,
         f16* __restrict__ wk16, f16* __restrict__ wv16,
         f16* __restrict__ wo16, f16* __restrict__ rf16)
{
    int bid = blockIdx.x;
    if (bid < 8192) {                       // x split
        int i = bid * 256 + threadIdx.x;
        float4 v = ((const float4*)x)[i];
        store_pair_h(xh, xl, (size_t)i * 4, v.x, v.y);
        store_pair_h(xh, xl, (size_t)i * 4 + 2, v.z, v.w);
    } else if (bid < 9216) {                // wq split
        int i = (bid - 8192) * 256 + threadIdx.x;
        float4 v = ((const float4*)wq)[i];
        store_pair_h(wqh, wql, (size_t)i * 4, v.x, v.y);
        store_pair_h(wqh, wql, (size_t)i * 4 + 2, v.z, v.w);
    } else if (bid < 10240) {               // wk conv
        int i = (bid - 9216) * 256 + threadIdx.x;
        float4 v = ((const float4*)wk)[i];
        store_h2(wk16, (size_t)i * 4, v.x, v.y);
        store_h2(wk16, (size_t)i * 4 + 2, v.z, v.w);
    } else if (bid < 11264) {               // wv conv
        int i = (bid - 10240) * 256 + threadIdx.x;
        float4 v = ((const float4*)wv)[i];
        store_h2(wv16, (size_t)i * 4, v.x, v.y);
        store_h2(wv16, (size_t)i * 4 + 2, v.z, v.w);
    } else if (bid < 12288) {               // wo conv
        int i = (bid - 11264) * 256 + threadIdx.x;
        float4 v = ((const float4*)wo)[i];
        store_h2(wo16, (size_t)i * 4, v.x, v.y);
        store_h2(wo16, (size_t)i * 4 + 2, v.z, v.w);
    } else {                                // rf conv (16 blocks)
        int i = (bid - 12288) * 256 + threadIdx.x;
        if (i < 4096) {
            float4 v = ((const float4*)rf)[i];
            store_h2(rf16, (size_t)i * 4, v.x, v.y);
            store_h2(rf16, (size_t)i * 4 + 2, v.z, v.w);
        }
    }
}

// ======== merged init: VT ones rows + KVT zero rows ========
__global__ void __launch_bounds__(256) init_kernel(f16* __restrict__ VT, f16* __restrict__ kvt)
{
    const int bh = blockIdx.x;
    const f16 one = __float2half_rn(1.f), zero = __float2half_rn(0.f);
    for (int i = threadIdx.x; i < 8 * T_; i += 256) {
        int r = i >> 12, t = i & 4095;
        VT[((size_t)bh * 80 + 64 + r) * T_ + t] = (r == 0) ? one : zero;
    }
    for (int i = threadIdx.x; i < 15 * FD_; i += 256)
        kvt[((size_t)bh * 80 + 65) * FD_ + i] = zero;
}

// ======== phi kernels (1-pass MMA; both rf halves per CTA) ========
#define PQ_A   0
#define PQ_B   16384
#define PQ_NP  49152
#define SMEM_PHIQ 50176
#define PK_A   0
#define PK_B   32768
#define PK_SC  49152
#define PK_NP  49664
#define SMEM_PHIK 50688

__device__ __forceinline__ void conv_tile_h1(const float* g, int ld, char* sm, int dst,
                                             float* np, int tid) {
    int r = tid >> 1, cb = (tid & 1) << 5;
    float s = 0.f;
    const float* gp = g + (size_t)r * ld + cb;
#pragma unroll
    for (int k = 0; k < 8; k++) {
        float4 v = *(const float4*)(gp + k * 4);
        s = fmaf(v.x, v.x, s); s = fmaf(v.y, v.y, s);
        s = fmaf(v.z, v.z, s); s = fmaf(v.w, v.w, s);
        uint32_t sw = SWZ((uint32_t)(r * 128 + (cb + k * 4) * 2));
        __half2 hp0 = __halves2half2(__float2half_rn(v.x), __float2half_rn(v.y));
        __half2 hp1 = __halves2half2(__float2half_rn(v.z), __float2half_rn(v.w));
        *(uint32_t*)(sm + dst + sw) = *(uint32_t*)&hp0;
        *(uint32_t*)(sm + dst + sw + 4) = *(uint32_t*)&hp1;
    }
    np[tid] = s;
}

__global__ void __launch_bounds__(256) phi_q_kernel(
    const float* __restrict__ Q, const f16* __restrict__ rf16,
    f16* __restrict__ Qf, float* __restrict__ scq)
{
    extern __shared__ char sm[];
    const uint32_t sb = smem_to_u32(sm);
    const int tid = threadIdx.x, wid = tid >> 5, lane = tid & 31;
    const int t0 = blockIdx.x << 7, bh = blockIdx.y;
    const int b = bh >> 4, h = bh & 15;
    float* np = (float*)(sm + PQ_NP);
#pragma unroll
    for (int i = 0; i < 8; i++) {
        int idx = tid + (i << 8), r = idx >> 3, c = idx & 7;
        cp_async16(sb + PQ_B + SWZ(r * 128 + c * 16), rf16 + (size_t)r * DH_ + c * 8);
    }
    cp_commit();
    conv_tile_h1(&Q[((size_t)(b * T_ + t0)) * D_ + h * DH_], D_, sm, PQ_A, np, tid);
    __syncthreads();
    if (tid < 128)
        scq[(size_t)bh * T_ + t0 + tid] = __expf(-0.5f * (np[2 * tid] + np[2 * tid + 1])) * 0.0625f;
    cp_wait<0>();
    __syncthreads();
    const int wt = (wid >> 2) << 6, wm = (wid & 3) << 5;
    const int lr = lane & 15, lc = lane >> 4, br = lane & 7, bk = (lane >> 3) & 1;
    for (int half = 0; half < 2; half++) {
        const int m0c = half << 7;
        const uint32_t bB = sb + PQ_B + (half << 14);
        float acc[4][4][4];
#pragma unroll
        for (int i = 0; i < 4; i++)
#pragma unroll
            for (int j = 0; j < 4; j++)
#pragma unroll
                for (int r = 0; r < 4; r++) acc[i][j][r] = 0.f;
#pragma unroll
        for (int ks = 0; ks < 4; ks++) {
            uint32_t a_[4][4], b_[4][2];
#pragma unroll
            for (int i = 0; i < 4; i++) {
                uint32_t o = SWZ((wt + i * 16 + lr) * 128 + ks * 32 + lc * 16);
                ldsm_x4(a_[i][0], a_[i][1], a_[i][2], a_[i][3], sb + PQ_A + o);
            }
#pragma unroll
            for (int j = 0; j < 4; j++) {
                uint32_t o = SWZ((wm + j * 8 + br) * 128 + ks * 32 + bk * 16);
                ldsm_x2(b_[j][0], b_[j][1], bB + o);
            }
#pragma unroll
            for (int i = 0; i < 4; i++)
#pragma unroll
                for (int j = 0; j < 4; j++)
                    mma_f16(acc[i][j], a_[i], b_[j]);
        }
#pragma unroll
        for (int i = 0; i < 4; i++) {
            int r0 = wt + i * 16 + (lane >> 2);
            size_t rb0 = ((size_t)bh * T_ + t0 + r0) * FD_ + m0c;
            size_t rb1 = rb0 + (size_t)8 * FD_;
#pragma unroll
            for (int j = 0; j < 4; j++) {
                int mc = wm + j * 8 + ((lane & 3) << 1);
                float sn0, cs0, sn1, cs1;
                fast_sincos(acc[i][j][0], sn0, cs0);
                fast_sincos(acc[i][j][1], sn1, cs1);
                store_h2(Qf, rb0 + mc, cs0, cs1);
                store_h2(Qf, rb0 + 256 + mc, sn0, sn1);
                fast_sincos(acc[i][j][2], sn0, cs0);
                fast_sincos(acc[i][j][3], sn1, cs1);
                store_h2(Qf, rb1 + mc, cs0, cs1);
                store_h2(Qf, rb1 + 256 + mc, sn0, sn1);
            }
        }
    }
}

__global__ void __launch_bounds__(256) phi_k_kernel(
    const float* __restrict__ Kg, const f16* __restrict__ rf16,
    const float* __restrict__ beta, f16* __restrict__ KfT)
{
    extern __shared__ char sm[];
    const uint32_t sb = smem_to_u32(sm);
    const int tid = threadIdx.x, wid = tid >> 5, lane = tid & 31;
    const int t0 = blockIdx.x << 7, bh = blockIdx.y;
    const int b = bh >> 4, h = bh & 15;
    float* scale = (float*)(sm + PK_SC);
    float* np = (float*)(sm + PK_NP);
    const float gamma = 1.f / beta[bh];
#pragma unroll
    for (int i = 0; i < 8; i++) {
        int idx = tid + (i << 8), r = idx >> 3, c = idx & 7;
        cp_async16(sb + PK_A + SWZ(r * 128 + c * 16), rf16 + (size_t)r * DH_ + c * 8);
    }
    cp_commit();
    conv_tile_h1(&Kg[((size_t)(b * T_ + t0)) * D_ + h * DH_], D_, sm, PK_B, np, tid);
    __syncthreads();
    if (tid < 128)
        scale[tid] = __expf(-0.5f * (np[2 * tid] + np[2 * tid + 1])) * 0.0625f * gamma;
    cp_wait<0>();
    __syncthreads();
    const int wm = (wid >> 2) << 6, wt = (wid & 3) << 5;
    const int lr = lane & 15, lc = lane >> 4, br = lane & 7, bk = (lane >> 3) & 1;
    for (int half = 0; half < 2; half++) {
        const int m0c = half << 7;
        const uint32_t bA = sb + PK_A + (half << 14);
        float acc[4][4][4];
#pragma unroll
        for (int i = 0; i < 4; i++)
#pragma unroll
            for (int j = 0; j < 4; j++)
#pragma unroll
                for (int r = 0; r < 4; r++) acc[i][j][r] = 0.f;
#pragma unroll
        for (int ks = 0; ks < 4; ks++) {
            uint32_t a_[4][4], b_[4][2];
#pragma unroll
            for (int i = 0; i < 4; i++) {
                uint32_t o = SWZ((wm + i * 16 + lr) * 128 + ks * 32 + lc * 16);
                ldsm_x4(a_[i][0], a_[i][1], a_[i][2], a_[i][3], bA + o);
            }
#pragma unroll
            for (int j = 0; j < 4; j++) {
                uint32_t o = SWZ((wt + j * 8 + br) * 128 + ks * 32 + bk * 16);
                ldsm_x2(b_[j][0], b_[j][1], sb + PK_B + o);
            }
#pragma unroll
            for (int i = 0; i < 4; i++)
#pragma unroll
                for (int j = 0; j < 4; j++)
                    mma_f16(acc[i][j], a_[i], b_[j]);
        }
#pragma unroll
        for (int i = 0; i < 4; i++) {
            int r0 = wm + i * 16 + (lane >> 2);
            size_t rc0 = ((size_t)bh * FD_ + m0c + r0) * T_ + t0;
            size_t rs0 = rc0 + (size_t)256 * T_;
            size_t rc1 = rc0 + (size_t)8 * T_, rs1 = rs0 + (size_t)8 * T_;
#pragma unroll
            for (int j = 0; j < 4; j++) {
                int tc = wt + j * 8 + ((lane & 3) << 1);
                float sc0 = scale[tc], sc1 = scale[tc + 1];
                float sn0, cs0, sn1, cs1;
                fast_sincos(acc[i][j][0], sn0, cs0);
                fast_sincos(acc[i][j][1], sn1, cs1);
                store_h2(KfT, rc0 + tc, cs0 * sc0, cs1 * sc1);
                store_h2(KfT, rs0 + tc, sn0 * sc0, sn1 * sc1);
                fast_sincos(acc[i][j][2], sn0, cs0);
                fast_sincos(acc[i][j][3], sn1, cs1);
                store_h2(KfT, rc1 + tc, cs0 * sc0, cs1 * sc1);
                store_h2(KfT, rs1 + tc, sn0 * sc0, sn1 * sc1);
            }
        }
    }
}

// ======== knorm / alphabeta / srow ========
__global__ void __launch_bounds__(256) knorm_kernel(const float* __restrict__ Kg,
                                                    float* __restrict__ sck)
{
    __shared__ float np[256];
    const int tid = threadIdx.x;
    const int t0 = blockIdx.x << 7, bh = blockIdx.y;
    const int b = bh >> 4, h = bh & 15;
    int r = tid >> 1, cb = (tid & 1) << 5;
    const float* gp = Kg + ((size_t)(b * T_ + t0 + r)) * D_ + h * DH_ + cb;
    float s = 0.f;
#pragma unroll
    for (int k = 0; k < 8; k++) {
        float4 v = *(const float4*)(gp + k * 4);
        s = fmaf(v.x, v.x, s); s = fmaf(v.y, v.y, s);
        s = fmaf(v.z, v.z, s); s = fmaf(v.w, v.w, s);
    }
    np[tid] = s;
    __syncthreads();
    if (tid < 128)
        sck[(size_t)bh * T_ + t0 + tid] = __expf(-0.5f * (np[2 * tid] + np[2 * tid + 1])) * 0.0625f;
}

__global__ void __launch_bounds__(256) alphabeta_kernel(const float* __restrict__ sck,
                                                        float* __restrict__ alpha,
                                                        float* __restrict__ beta)
{
    __shared__ float rs[256], rm[256];
    const int bh = blockIdx.x, tid = threadIdx.x;
    float s = 0.f, m = 0.f;
    for (int i = tid; i < T_; i += 256) {
        float v = sck[(size_t)bh * T_ + i];
        s += v; m = fmaxf(m, v);
    }
    rs[tid] = s; rm[tid] = m;
    __syncthreads();
    for (int o = 128; o; o >>= 1) {
        if (tid < o) { rs[tid] += rs[tid + o]; rm[tid] = fmaxf(rm[tid], rm[tid + o]); }
        __syncthreads();
    }
    if (tid == 0) {
        alpha[bh] = 1.f / fmaxf(rs[0], 1e-30f);
        beta[bh]  = fmaxf(rm[0], 1e-37f);
    }
}

__global__ void __launch_bounds__(256) srow_kernel(const float* __restrict__ scq,
                                                   const float* __restrict__ alpha,
                                                   float* __restrict__ srow)
{
    int row = blockIdx.x * 256 + threadIdx.x;
    int b = row >> 12, t = row & 4095;
    float m = 0.f;
#pragma unroll
    for (int h = 0; h < H_; h++) {
        int bh = b * H_ + h;
        m = fmaxf(m, scq[(size_t)bh * T_ + t] / alpha[bh]);
    }
    srow[row] = fmaxf(m * 1e6f, 1e-30f);
}

// ======== kv: KfT'(fp16) x VT(fp16, 72 rows)^T, 1-pass, fused Ksum ========
#define KA   0
#define KB   16384
#define KBUF 26624
#define SMEM_KV (2*KBUF)

__global__ void __launch_bounds__(256) kv_gemm(
    const f16* __restrict__ Am, const f16* __restrict__ Bm,
    const float* __restrict__ alpha, const float* __restrict__ beta,
    f16* __restrict__ kvt)
{
    extern __shared__ char sm[];
    const uint32_t sb = smem_to_u32(sm);
    const int tid = threadIdx.x, wid = tid >> 5, lane = tid & 31;
    const int m0 = blockIdx.x << 7, bh = blockIdx.y;
    const size_t ab = (size_t)bh * FD_ + m0, bb = (size_t)bh * 80;
    const int wm = (wid >> 1) << 5, wn = (wid & 1) * 40;
    const int lr = lane & 15, lc = lane >> 4, br = lane & 7, bk = (lane >> 3) & 1;
    float acc[2][5][4];
#pragma unroll
    for (int i = 0; i < 2; i++)
#pragma unroll
        for (int j = 0; j < 5; j++)
#pragma unroll
            for (int r = 0; r < 4; r++) acc[i][j][r] = 0.f;
    auto load = [&](int kc, int buf) {
        uint32_t base = sb + buf * KBUF;
        int ke = kc << 6;
#pragma unroll
        for (int i = 0; i < 4; i++) {
            int idx = tid + (i << 8), r = idx >> 3, c = idx & 7;
            cp_async16(base + KA + SWZ(r * 128 + c * 16), Am + (ab + r) * T_ + ke + c * 8);
        }
#pragma unroll
        for (int i = 0; i < 3; i++) {
            int idx = tid + (i << 8);
            if (idx < 576) {
                int r = idx >> 3, c = idx & 7;
                cp_async16(base + KB + SWZ(r * 128 + c * 16), Bm + (bb + r) * T_ + ke + c * 8);
            }
        }
    };
    load(0, 0); cp_commit();
    for (int kc = 0; kc < T_ / 64; kc++) {
        int cur = kc & 1;
        if (kc + 1 < T_ / 64) { load(kc + 1, cur ^ 1); cp_commit(); cp_wait<1>(); }
        else cp_wait<0>();
        __syncthreads();
        uint32_t bA = sb + cur * KBUF;
#pragma unroll
        for (int ks = 0; ks < 4; ks++) {
            uint32_t a_[2][4], b_[5][2];
#pragma unroll
            for (int i = 0; i < 2; i++) {
                uint32_t o = SWZ((wm + i * 16 + lr) * 128 + ks * 32 + lc * 16);
                ldsm_x4(a_[i][0], a_[i][1], a_[i][2], a_[i][3], bA + KA + o);
            }
#pragma unroll
            for (int j = 0; j < 5; j++) {
                uint32_t o = SWZ((wn + j * 8 + br) * 128 + ks * 32 + bk * 16);
                ldsm_x2(b_[j][0], b_[j][1], bA + KB + o);
            }
#pragma unroll
            for (int i = 0; i < 2; i++)
#pragma unroll
                for (int j = 0; j < 5; j++)
                    mma_f16(acc[i][j], a_[i], b_[j]);
        }
        __syncthreads();
    }
    float* stage = (float*)sm;
#pragma unroll
    for (int i = 0; i < 2; i++) {
        int row = wm + i * 16 + (lane >> 2);
#pragma unroll
        for (int j = 0; j < 5; j++) {
            int col = wn + j * 8 + ((lane & 3) << 1);
            stage[col * 132 + row]           = acc[i][j][0];
            stage[(col + 1) * 132 + row]     = acc[i][j][1];
            stage[col * 132 + row + 8]       = acc[i][j][2];
            stage[(col + 1) * 132 + row + 8] = acc[i][j][3];
        }
    }
    __syncthreads();
    float av = alpha[bh] * beta[bh];
    int v = tid >> 2, fs = (tid & 3) << 5;
#pragma unroll
    for (int p = 0; p < 16; p++) {
        int f = fs + p * 2;
        store_h2(kvt, ((size_t)bh * 80 + v) * FD_ + m0 + f,
                 stage[v * 132 + f] * av, stage[v * 132 + f + 1] * av);
    }
    if (tid < 64) {
        int f = tid * 2;
        store_h2(kvt, ((size_t)bh * 80 + 64) * FD_ + m0 + f,
                 stage[64 * 132 + f] * av, stage[64 * 132 + f + 1] * av);
    }
}

// ======== qkv: Qf(single) x KVT'[80], 1-pass; epilogue Z + scales ========
#define QA   0
#define QB   16384
#define QBUF 26624
#define SMEM_QKV (2*QBUF)

__global__ void __launch_bounds__(256) qkv_gemm(
    const f16* __restrict__ Am, const f16* __restrict__ Bm,
    const float* __restrict__ scq, const float* __restrict__ alpha,
    const float* __restrict__ srow, f16* __restrict__ oh)
{
    extern __shared__ char sm[];
    __shared__ float zsm[128];
    const uint32_t sb = smem_to_u32(sm);
    const int tid = threadIdx.x, wid = tid >> 5, lane = tid & 31;
    const int t0 = blockIdx.x << 7, bh = blockIdx.y;
    const int b = bh >> 4, h = bh & 15;
    const size_t ab = (size_t)bh * T_ + t0, bb = (size_t)bh * 80;
    const int wm = (wid >> 1) << 5, wn = (wid & 1) * 40;
    const int lr = lane & 15, lc = lane >> 4, br = lane & 7, bk = (lane >> 3) & 1;
    float acc[2][5][4];
#pragma unroll
    for (int i = 0; i < 2; i++)
#pragma unroll
        for (int j = 0; j < 5; j++)
#pragma unroll
            for (int r = 0; r < 4; r++) acc[i][j][r] = 0.f;
    auto load = [&](int kc, int buf) {
        uint32_t base = sb + buf * QBUF;
        int ke = kc << 6;
#pragma unroll
        for (int i = 0; i < 4; i++) {
            int idx = tid + (i << 8), r = idx >> 3, c = idx & 7;
            cp_async16(base + QA + SWZ(r * 128 + c * 16), Am + (ab + r) * FD_ + ke + c * 8);
        }
#pragma unroll
        for (int i = 0; i < 3; i++) {
            int idx = tid + (i << 8);
            if (idx < 640) {
                int r = idx >> 3, c = idx & 7;
                cp_async16(base + QB + SWZ(r * 128 + c * 16), Bm + (bb + r) * FD_ + ke + c * 8);
            }
        }
    };
    load(0, 0); cp_commit();
    for (int kc = 0; kc < 8; kc++) {
        int cur = kc & 1;
        if (kc + 1 < 8) { load(kc + 1, cur ^ 1); cp_commit(); cp_wait<1>(); }
        else cp_wait<0>();
        __syncthreads();
        uint32_t bA = sb + cur * QBUF;
#pragma unroll
        for (int ks = 0; ks < 4; ks++) {
            uint32_t a_[2][4], b_[5][2];
#pragma unroll
            for (int i = 0; i < 2; i++) {
                uint32_t o = SWZ((wm + i * 16 + lr) * 128 + ks * 32 + lc * 16);
                ldsm_x4(a_[i][0], a_[i][1], a_[i][2], a_[i][3], bA + QA + o);
            }
#pragma unroll
            for (int j = 0; j < 5; j++) {
                uint32_t o = SWZ((wn + j * 8 + br) * 128 + ks * 32 + bk * 16);
                ldsm_x2(b_[j][0], b_[j][1], bA + QB + o);
            }
#pragma unroll
            for (int i = 0; i < 2; i++)
#pragma unroll
                for (int j = 0; j < 5; j++)
                    mma_f16(acc[i][j], a_[i], b_[j]);
        }
        __syncthreads();
    }
    if (wn == 40 && (lane & 3) == 0) {
#pragma unroll
        for (int i = 0; i < 2; i++) {
            int row = wm + i * 16 + (lane >> 2);
            zsm[row] = acc[i][3][0];
            zsm[row + 8] = acc[i][3][2];
        }
    }
    __syncthreads();
    float av = alpha[bh];
#pragma unroll
    for (int i = 0; i < 2; i++) {
#pragma unroll
        for (int half = 0; half < 2; half++) {
            int row = wm + i * 16 + (lane >> 2) + half * 8;
            float sq = scq[ab + row];
            float Zt = sq * zsm[row] / av;
            float d = fmaxf(Zt, 1e-6f);
            float mult = sq / (av * d * srow[(size_t)b * T_ + t0 + row]);
#pragma unroll
            for (int j = 0; j < 5; j++) {
                int col = wn + j * 8 + ((lane & 3) << 1);
                if (col < 64) {
                    size_t g0 = ((size_t)(b * T_ + t0 + row)) * D_ + h * DH_ + col;
                    store_h2(oh, g0, acc[i][j][half * 2] * mult, acc[i][j][half * 2 + 1] * mult);
                }
            }
        }
    }
}

// ======== launch ========
extern "C" void kernel_launch(void* const* d_in, const int* in_sizes, int n_in,
                              void* d_out, int out_size)
{
    const float* x  = (const float*)d_in[0];
    const float* wq = (const float*)d_in[1];
    const float* wk = (const float*)d_in[2];
    const float* wv = (const float*)d_in[3];
    const float* wo = (const float*)d_in[4];
    const float* rf = (const float*)d_in[5];
    float* out = (float*)d_out;

    float* fb = nullptr; cudaGetSymbolAddress((void**)&fb, g_buf);
    bf16*  bb = nullptr; cudaGetSymbolAddress((void**)&bb, g_bf);

    float *Qp = fb + OFF_Q, *Kp = fb + OFF_K;
    float *SCQ = fb + OFF_SCQ, *SCK = fb + OFF_SCK;
    float *ALP = fb + OFF_AL, *BET = fb + OFF_BE, *SR = fb + OFF_SR;
    f16 *xh = (f16*)(bb + BO_XH), *xl = (f16*)(bb + BO_XL);
    f16 *wqh = (f16*)(bb + BO_WQH), *wql = (f16*)(bb + BO_WQL);
    f16 *wk16 = (f16*)(bb + BO_WK);
    f16 *wv16 = (f16*)(bb + BO_WV), *wo16 = (f16*)(bb + BO_WO);
    f16 *rf16 = (f16*)(bb + BO_RF);
    f16 *Qf = (f16*)(bb + BO_QF);
    f16 *KfT = (f16*)(bb + BO_KFT);
    f16 *VT = (f16*)(bb + BO_VT);
    f16 *KVT = (f16*)(bb + BO_KVT);
    f16 *ah = (f16*)(bb + BO_AH);

    cudaFuncSetAttribute(proj_all, cudaFuncAttributeMaxDynamicSharedMemorySize, SMEM_PROJ);
    cudaFuncSetAttribute(gemm1, cudaFuncAttributeMaxDynamicSharedMemorySize, SMEM_G1);
    cudaFuncSetAttribute(phi_q_kernel, cudaFuncAttributeMaxDynamicSharedMemorySize, SMEM_PHIQ);
    cudaFuncSetAttribute(phi_k_kernel, cudaFuncAttributeMaxDynamicSharedMemorySize, SMEM_PHIK);
    cudaFuncSetAttribute(kv_gemm, cudaFuncAttributeMaxDynamicSharedMemorySize, SMEM_KV);
    cudaFuncSetAttribute(qkv_gemm, cudaFuncAttributeMaxDynamicSharedMemorySize, SMEM_QKV);

    // merged conversions + init
    conv_all<<<12304, 256>>>(x, wq, wk, wv, wo, rf,
                             xh, xl, wqh, wql, wk16, wv16, wo16, rf16);
    init_kernel<<<BH_, 256>>>(VT, KVT);

    // fused Q/K/V projections (z = 0/1/2)
    proj_all<<<dim3(8, 64, 3), 256, SMEM_PROJ>>>(xh, xl, wqh, wql, wk16, wv16, Qp, Kp, VT);

    dim3 gPhi(T_ / 128, BH_);
    phi_q_kernel<<<gPhi, 256, SMEM_PHIQ>>>(Qp, rf16, Qf, SCQ);
    knorm_kernel<<<gPhi, 256>>>(Kp, SCK);
    alphabeta_kernel<<<BH_, 256>>>(SCK, ALP, BET);
    phi_k_kernel<<<gPhi, 256, SMEM_PHIK>>>(Kp, rf16, BET, KfT);

    kv_gemm<<<dim3(FD_ / 128, BH_), 256, SMEM_KV>>>(KfT, VT, ALP, BET, KVT);
    srow_kernel<<<(B_ * T_) / 256, 256>>>(SCQ, ALP, SR);

    qkv_gemm<<<dim3(T_ / 128, BH_), 256, SMEM_QKV>>>(Qf, KVT, SCQ, ALP, SR, ah);

    gemm1<<<dim3(8, 64), 256, SMEM_G1>>>(ah, wo16, SR, out, B_ * T_, D_, D_);
}